// round 11
// baseline (speedup 1.0000x reference)
#include <cuda_runtime.h>
#include <cuda_fp16.h>

#define B_ 8
#define T_ 2048
#define E_ 1024
#define M_ (B_ * T_)

#define BM 128
#define BN 128
#define BK 64
#define TB 128                           // 4 warps, warp tile 64x64
#define NSTAGE 3
#define ASUB 16384u                      // 128x64 fp16
#define STAGE_BYTES (2 * ASUB)           // 32768
#define DSMEM (NSTAGE * STAGE_BYTES)     // 98304
#define QK_SCALE 0.17677669529663687f    // 1024^-0.25

// ---------------- scratch ----------------
__device__ __half g_x[3][(size_t)M_ * E_];
__device__ __half g_w[3][(size_t)E_ * E_];
__device__ __half g_Q[(size_t)M_ * E_];
__device__ __half g_K[(size_t)M_ * E_];
__device__ __half g_V[(size_t)M_ * E_];
__device__ __half g_Vt[(size_t)B_ * E_ * T_];
__device__ __half g_P[(size_t)B_ * T_ * T_];   // exp(scores), unnormalized
__device__ float  g_rinv[(size_t)M_];          // 1 / rowsum

// ---------------- helpers ----------------
__device__ __forceinline__ unsigned smem_u32(const void* p) {
    return (unsigned)__cvta_generic_to_shared(p);
}
// 128B rows, 8x16B chunks, SW128 xor swizzle: conflict-free for ldmatrix
__device__ __forceinline__ unsigned swz128(int r, int c) {
    return (unsigned)(r * 128 + ((c ^ (r & 7)) * 16));
}
__device__ __forceinline__ void cp_async16(unsigned s, const void* g) {
    asm volatile("cp.async.cg.shared.global [%0], [%1], 16;" :: "r"(s), "l"(g) : "memory");
}
__device__ __forceinline__ void ldsm4(unsigned* r, unsigned addr) {
    asm volatile("ldmatrix.sync.aligned.m8n8.x4.shared.b16 {%0,%1,%2,%3}, [%4];"
                 : "=r"(r[0]), "=r"(r[1]), "=r"(r[2]), "=r"(r[3]) : "r"(addr));
}
__device__ __forceinline__ void mma16816(float* c, const unsigned* a, unsigned b0, unsigned b1) {
    asm volatile(
        "mma.sync.aligned.m16n8k16.row.col.f32.f16.f16.f32 "
        "{%0,%1,%2,%3}, {%4,%5,%6,%7}, {%8,%9}, {%0,%1,%2,%3};"
        : "+f"(c[0]), "+f"(c[1]), "+f"(c[2]), "+f"(c[3])
        : "r"(a[0]), "r"(a[1]), "r"(a[2]), "r"(a[3]), "r"(b0), "r"(b1));
}

// ---------------- single-pass fp16 mma.sync GEMM body (128x128 tile) --------
// D[m0..+128, n0..+128] = A * B^T (both fp16, K-major). 4 warps, warp tile 64x64.
// EPI 2: scale + fp16 to Ch
// EPI 3: exp(v) with causal mask (col > row -> 0), fp16 to Ch
// EPI 4: fp32 to Cf, scaled by Rinv[row]
template <int EPI>
__device__ __forceinline__ void gemm_body(
    const __half* __restrict__ A, const __half* __restrict__ Bs,
    int lda, int ldb, int m0, int n0, int kTiles, float scale,
    float* __restrict__ Cf, __half* __restrict__ Ch, int ldc,
    const float* __restrict__ Rinv)
{
    extern __shared__ __align__(128) char smem[];
    const unsigned sbase = smem_u32(smem);
    const int tid = threadIdx.x;
    const int wid = tid >> 5;
    const int lane = tid & 31;
    const int wm = wid & 1;        // 2 m-tiles of 64
    const int wn = wid >> 1;       // 2 n-tiles of 64

    // per-ks base ldmatrix offsets; row +16 adds exactly 2048 bytes (swizzle-safe)
    unsigned abase[4], bbase[4];
#pragma unroll
    for (int ks = 0; ks < 4; ++ks) {
        abase[ks] = swz128(wm * 64 + (lane & 15), ks * 2 + (lane >> 4));
        bbase[ks] = ASUB + swz128(wn * 64 + ((lane >> 4) & 1) * 8 + (lane & 7),
                                  ks * 2 + ((lane >> 3) & 1));
    }

    float acc[4][8][4];
#pragma unroll
    for (int i = 0; i < 4; ++i)
#pragma unroll
        for (int j = 0; j < 8; ++j)
#pragma unroll
            for (int e = 0; e < 4; ++e) acc[i][j][e] = 0.0f;

    const int cc = tid & 7;        // chunk within row
    const int rr = tid >> 3;       // base row (0..15)

    auto load_stage = [&](int k0, int buf) {
        const unsigned sb = sbase + buf * STAGE_BYTES;
#pragma unroll
        for (int j = 0; j < 8; ++j) {          // A: 128 rows
            const int r = rr + j * 16;
            cp_async16(sb + swz128(r, cc),
                       A + (size_t)(m0 + r) * lda + k0 + cc * 8);
        }
#pragma unroll
        for (int j = 0; j < 8; ++j) {          // B: 128 rows
            const int r = rr + j * 16;
            cp_async16(sb + ASUB + swz128(r, cc),
                       Bs + (size_t)(n0 + r) * ldb + k0 + cc * 8);
        }
    };

    auto compute_ks = [&](unsigned sb, int ks) {
        unsigned a[4][4], b[4][4];
#pragma unroll
        for (int mi = 0; mi < 4; ++mi) ldsm4(a[mi], sb + abase[ks] + mi * 2048);
#pragma unroll
        for (int jp = 0; jp < 4; ++jp) ldsm4(b[jp], sb + bbase[ks] + jp * 2048);
#pragma unroll
        for (int mi = 0; mi < 4; ++mi)
#pragma unroll
            for (int ni = 0; ni < 8; ++ni)
                mma16816(acc[mi][ni], a[mi],
                         b[ni >> 1][(ni & 1) * 2], b[ni >> 1][(ni & 1) * 2 + 1]);
    };

    load_stage(0, 0);
    asm volatile("cp.async.commit_group;" ::: "memory");
    if (kTiles > 1) load_stage(BK, 1);
    asm volatile("cp.async.commit_group;" ::: "memory");

    for (int it = 0; it < kTiles; ++it) {
        asm volatile("cp.async.wait_group 1;" ::: "memory");
        __syncthreads();
        const unsigned sb = sbase + (it % NSTAGE) * STAGE_BYTES;
        compute_ks(sb, 0);
        if (it + 2 < kTiles) load_stage((it + 2) * BK, (it + 2) % NSTAGE);
        asm volatile("cp.async.commit_group;" ::: "memory");
        compute_ks(sb, 1);
        compute_ks(sb, 2);
        compute_ks(sb, 3);
    }

    // epilogue
    const int g = lane >> 2, tig = lane & 3;
#pragma unroll
    for (int mi = 0; mi < 4; ++mi) {
#pragma unroll
        for (int ni = 0; ni < 8; ++ni) {
            const int row = m0 + wm * 64 + mi * 16 + g;
            const int col = n0 + wn * 64 + ni * 8 + tig * 2;
#pragma unroll
            for (int h = 0; h < 2; ++h) {
                const int r = row + h * 8;
                float v0 = acc[mi][ni][2 * h + 0];
                float v1 = acc[mi][ni][2 * h + 1];
                if (EPI == 2) {
                    __half2 hh;
                    hh.x = __float2half(v0 * scale);
                    hh.y = __float2half(v1 * scale);
                    *(__half2*)(Ch + (size_t)r * ldc + col) = hh;
                } else if (EPI == 3) {
                    __half2 hh;
                    hh.x = (col     <= r) ? __float2half(__expf(v0)) : __half(0.0f);
                    hh.y = (col + 1 <= r) ? __float2half(__expf(v1)) : __half(0.0f);
                    *(__half2*)(Ch + (size_t)r * ldc + col) = hh;
                } else {
                    const float rv = Rinv[r];
                    *(float2*)(Cf + (size_t)r * ldc + col) = make_float2(v0 * rv, v1 * rv);
                }
            }
        }
    }
}

// ---------------- kernels ----------------
__global__ void __launch_bounds__(TB, 2)
proj_kernel()
{
    const int z = blockIdx.z;
    const int m0 = blockIdx.y * BM;
    const int n0 = blockIdx.x * BN;
    __half* dst = (z == 0) ? g_Q : (z == 1) ? g_K : g_V;
    const float scale = (z < 2) ? QK_SCALE : 1.0f;
    gemm_body<2>(g_x[z], g_w[z], E_, E_, m0, n0, E_ / BK, scale, nullptr, dst, E_, nullptr);
}

__global__ void __launch_bounds__(TB, 2)
scores_kernel()
{
    if ((int)blockIdx.x > (int)blockIdx.y) return;   // fully above causal diagonal
    const int b = blockIdx.z;
    const size_t qo = (size_t)b * T_ * E_;
    gemm_body<3>(g_Q + qo, g_K + qo, E_, E_,
                 blockIdx.y * BM, blockIdx.x * BN, E_ / BK, 1.0f,
                 nullptr, g_P + (size_t)b * T_ * T_, T_, nullptr);
}

__global__ void __launch_bounds__(TB, 2)
out_kernel(float* __restrict__ out)
{
    const int b = blockIdx.z;
    // reversed y: heaviest (largest-kT) blocks get the lowest block ids -> start first
    const int m0 = ((int)gridDim.y - 1 - (int)blockIdx.y) * BM;
    const int kT = (m0 + BM) / BK;   // causal clamp: P cols beyond m0+127 are zero
    gemm_body<4>(g_P + (size_t)b * T_ * T_, g_Vt + (size_t)b * E_ * T_,
                 T_, T_, m0, blockIdx.x * BN, kT, 1.0f,
                 out + (size_t)b * T_ * E_, nullptr, E_, g_rinv + (size_t)b * T_);
}

__global__ void __launch_bounds__(256)
convert3_kernel(const float* __restrict__ a, const float* __restrict__ b,
                const float* __restrict__ c, __half* __restrict__ o0,
                __half* __restrict__ o1, __half* __restrict__ o2, int n4)
{
    const float* in = (blockIdx.z == 0) ? a : (blockIdx.z == 1) ? b : c;
    __half* out = (blockIdx.z == 0) ? o0 : (blockIdx.z == 1) ? o1 : o2;
    int i = blockIdx.x * blockDim.x + threadIdx.x;
    const int stride = gridDim.x * blockDim.x;
    for (; i < n4; i += stride) {
        float4 x = ((const float4*)in)[i];
        __half2 h0; h0.x = __float2half(x.x); h0.y = __float2half(x.y);
        __half2 h1; h1.x = __float2half(x.z); h1.y = __float2half(x.w);
        ((__half2*)out)[2 * i] = h0;
        ((__half2*)out)[2 * i + 1] = h1;
    }
}

// 64x64 tile, half2 vectorized both sides
__global__ void __launch_bounds__(256)
transpose_v_kernel()
{
    __shared__ __half tile[64][65];
    const int b = blockIdx.z;
    const int e0 = blockIdx.x * 64;
    const int t0 = blockIdx.y * 64;
    const int tx = threadIdx.x & 31;   // half2 column index
    const int ty = threadIdx.x >> 5;   // 0..7
    const __half2* src2 = (const __half2*)(g_V + (size_t)b * T_ * E_);
#pragma unroll
    for (int k = 0; k < 8; ++k) {
        int row = ty + k * 8;                       // t offset
        __half2 v = src2[((size_t)(t0 + row) * E_ + e0) / 2 + tx];
        tile[row][2 * tx]     = v.x;
        tile[row][2 * tx + 1] = v.y;
    }
    __syncthreads();
    __half2* dst2 = (__half2*)(g_Vt + (size_t)b * E_ * T_);
#pragma unroll
    for (int k = 0; k < 8; ++k) {
        int erow = ty + k * 8;                      // e offset
        __half2 w;
        w.x = tile[2 * tx][erow];
        w.y = tile[2 * tx + 1][erow];
        dst2[((size_t)(e0 + erow) * T_ + t0) / 2 + tx] = w;
    }
}

// 1 / sum of each row of g_P (valid length = row + 1; tail is zero anyway)
__global__ void __launch_bounds__(256)
rowsum_kernel()
{
    const int i = blockIdx.x;
    const int b = blockIdx.y;
    const __half* ph = g_P + ((size_t)b * T_ + i) * T_;
    const int L = i + 1;
    const int tid = threadIdx.x;
    __shared__ float red[8];

    float s = 0.0f;
    for (int j = tid; j < L; j += 256) s += __half2float(ph[j]);
#pragma unroll
    for (int o = 16; o > 0; o >>= 1) s += __shfl_xor_sync(0xffffffffu, s, o);
    if ((tid & 31) == 0) red[tid >> 5] = s;
    __syncthreads();
    if (tid == 0) {
        float ss = 0.0f;
#pragma unroll
        for (int w = 0; w < 8; ++w) ss += red[w];
        g_rinv[(size_t)b * T_ + i] = 1.0f / ss;
    }
}

// ---------------- launch ----------------
extern "C" void kernel_launch(void* const* d_in, const int* in_sizes, int n_in,
                              void* d_out, int out_size)
{
    const float* q  = (const float*)d_in[0];
    const float* k  = (const float*)d_in[1];
    const float* v  = (const float*)d_in[2];
    const float* Wq = (const float*)d_in[3];
    const float* Wk = (const float*)d_in[4];
    const float* Wv = (const float*)d_in[5];
    float* out = (float*)d_out;

    cudaFuncSetAttribute(proj_kernel,   cudaFuncAttributeMaxDynamicSharedMemorySize, DSMEM);
    cudaFuncSetAttribute(scores_kernel, cudaFuncAttributeMaxDynamicSharedMemorySize, DSMEM);
    cudaFuncSetAttribute(out_kernel,    cudaFuncAttributeMaxDynamicSharedMemorySize, DSMEM);

    __half *x0, *w0;
    cudaGetSymbolAddress((void**)&x0, g_x);
    cudaGetSymbolAddress((void**)&w0, g_w);
    __half *x1 = x0 + (size_t)M_ * E_, *x2 = x1 + (size_t)M_ * E_;
    __half *w1 = w0 + (size_t)E_ * E_, *w2 = w1 + (size_t)E_ * E_;

    const int n4x = M_ * E_ / 4;
    const int n4w = E_ * E_ / 4;
    convert3_kernel<<<dim3(1024, 1, 3), 256>>>(q, k, v, x0, x1, x2, n4x);
    convert3_kernel<<<dim3(256, 1, 3), 256>>>(Wq, Wk, Wv, w0, w1, w2, n4w);

    proj_kernel<<<dim3(E_ / BN, M_ / BM, 3), TB, DSMEM>>>();
    transpose_v_kernel<<<dim3(E_ / 64, T_ / 64, B_), 256>>>();
    scores_kernel<<<dim3(T_ / BN, T_ / BM, B_), TB, DSMEM>>>();
    rowsum_kernel<<<dim3(T_, B_), 256>>>();
    out_kernel<<<dim3(E_ / BN, T_ / BM, B_), TB, DSMEM>>>(out);
}

// round 15
// speedup vs baseline: 1.0434x; 1.0434x over previous
#include <cuda_runtime.h>
#include <cuda_fp16.h>

#define B_ 8
#define T_ 2048
#define E_ 1024
#define M_ (B_ * T_)

#define BM 128
#define BN 128
#define BK 64
#define TB 256
#define NSTAGE 3
#define ASUB 16384u                      // 128x64 fp16
#define STAGE_BYTES (2 * ASUB)           // 32768
#define DSMEM (NSTAGE * STAGE_BYTES)     // 98304
#define QK_SCALE 0.17677669529663687f    // 1024^-0.25

// ---------------- scratch ----------------
__device__ __half g_x[3][(size_t)M_ * E_];
__device__ __half g_w[3][(size_t)E_ * E_];
__device__ __half g_Q[(size_t)M_ * E_];
__device__ __half g_K[(size_t)M_ * E_];
__device__ __half g_V[(size_t)M_ * E_];
__device__ __half g_Vt[(size_t)B_ * E_ * T_];
__device__ __half g_P[(size_t)B_ * T_ * T_];   // exp(scores), unnormalized
__device__ float  g_rsum[(size_t)M_];          // rowsum of g_P (atomic accum)

// ---------------- helpers ----------------
__device__ __forceinline__ unsigned smem_u32(const void* p) {
    return (unsigned)__cvta_generic_to_shared(p);
}
// 128B rows, 8x16B chunks, SW128 xor swizzle: conflict-free for ldmatrix
__device__ __forceinline__ unsigned swz128(int r, int c) {
    return (unsigned)(r * 128 + ((c ^ (r & 7)) * 16));
}
__device__ __forceinline__ void cp_async16(unsigned s, const void* g) {
    asm volatile("cp.async.cg.shared.global [%0], [%1], 16;" :: "r"(s), "l"(g) : "memory");
}
__device__ __forceinline__ void ldsm4(unsigned* r, unsigned addr) {
    asm volatile("ldmatrix.sync.aligned.m8n8.x4.shared.b16 {%0,%1,%2,%3}, [%4];"
                 : "=r"(r[0]), "=r"(r[1]), "=r"(r[2]), "=r"(r[3]) : "r"(addr));
}
__device__ __forceinline__ void mma16816(float* c, const unsigned* a, unsigned b0, unsigned b1) {
    asm volatile(
        "mma.sync.aligned.m16n8k16.row.col.f32.f16.f16.f32 "
        "{%0,%1,%2,%3}, {%4,%5,%6,%7}, {%8,%9}, {%0,%1,%2,%3};"
        : "+f"(c[0]), "+f"(c[1]), "+f"(c[2]), "+f"(c[3])
        : "r"(a[0]), "r"(a[1]), "r"(a[2]), "r"(a[3]), "r"(b0), "r"(b1));
}

// ---------------- single-pass fp16 mma.sync GEMM body (128x128 tile) --------
// D[m0..+128, n0..+128] = A * B^T (both fp16, K-major). Warp tile 64x32.
// EPI 2: scale + fp16 to Ch
// EPI 3: exp(v) with causal mask (col > row -> 0), fp16 to Ch, rowsum atomics to Rsum
// EPI 4: fp32 to Cf, scaled by 1/Rsum[row]
template <int EPI>
__device__ __forceinline__ void gemm_body(
    const __half* __restrict__ A, const __half* __restrict__ Bs,
    int lda, int ldb, int m0, int n0, int kTiles, float scale,
    float* __restrict__ Cf, __half* __restrict__ Ch, int ldc,
    float* __restrict__ Rsum)
{
    extern __shared__ __align__(128) char smem[];
    const unsigned sbase = smem_u32(smem);
    const int tid = threadIdx.x;
    const int wid = tid >> 5;
    const int lane = tid & 31;
    const int wm = wid & 1;        // 2 m-tiles of 64
    const int wn = wid >> 1;       // 4 n-tiles of 32

    // per-ks base ldmatrix offsets; row +16 adds exactly 2048 bytes (swizzle-safe)
    unsigned abase[4], bbase[4];
#pragma unroll
    for (int ks = 0; ks < 4; ++ks) {
        abase[ks] = swz128(wm * 64 + (lane & 15), ks * 2 + (lane >> 4));
        bbase[ks] = ASUB + swz128(wn * 32 + ((lane >> 4) & 1) * 8 + (lane & 7),
                                  ks * 2 + ((lane >> 3) & 1));
    }

    float acc[4][4][4];
#pragma unroll
    for (int i = 0; i < 4; ++i)
#pragma unroll
        for (int j = 0; j < 4; ++j)
#pragma unroll
            for (int e = 0; e < 4; ++e) acc[i][j][e] = 0.0f;

    const int cc = tid & 7;        // chunk within row
    const int rr = tid >> 3;       // base row (0..31)

    auto load_stage = [&](int k0, int buf) {
        const unsigned sb = sbase + buf * STAGE_BYTES;
#pragma unroll
        for (int j = 0; j < 4; ++j) {          // A: 128 rows
            const int r = rr + j * 32;
            cp_async16(sb + swz128(r, cc),
                       A + (size_t)(m0 + r) * lda + k0 + cc * 8);
        }
#pragma unroll
        for (int j = 0; j < 4; ++j) {          // B: 128 rows
            const int r = rr + j * 32;
            cp_async16(sb + ASUB + swz128(r, cc),
                       Bs + (size_t)(n0 + r) * ldb + k0 + cc * 8);
        }
    };

    auto compute_ks = [&](unsigned sb, int ks) {
        unsigned a[4][4], b[2][4];
#pragma unroll
        for (int mi = 0; mi < 4; ++mi) ldsm4(a[mi], sb + abase[ks] + mi * 2048);
#pragma unroll
        for (int jp = 0; jp < 2; ++jp) ldsm4(b[jp], sb + bbase[ks] + jp * 2048);
#pragma unroll
        for (int mi = 0; mi < 4; ++mi)
#pragma unroll
            for (int ni = 0; ni < 4; ++ni)
                mma16816(acc[mi][ni], a[mi],
                         b[ni >> 1][(ni & 1) * 2], b[ni >> 1][(ni & 1) * 2 + 1]);
    };

    load_stage(0, 0);
    asm volatile("cp.async.commit_group;" ::: "memory");
    if (kTiles > 1) load_stage(BK, 1);
    asm volatile("cp.async.commit_group;" ::: "memory");

    for (int it = 0; it < kTiles; ++it) {
        asm volatile("cp.async.wait_group 1;" ::: "memory");
        __syncthreads();
        const unsigned sb = sbase + (it % NSTAGE) * STAGE_BYTES;
        compute_ks(sb, 0);
        if (it + 2 < kTiles) load_stage((it + 2) * BK, (it + 2) % NSTAGE);
        asm volatile("cp.async.commit_group;" ::: "memory");
        compute_ks(sb, 1);
        compute_ks(sb, 2);
        compute_ks(sb, 3);
    }

    // epilogue
    const int g = lane >> 2, tig = lane & 3;
    if (EPI == 2) {
#pragma unroll
        for (int mi = 0; mi < 4; ++mi)
#pragma unroll
            for (int ni = 0; ni < 4; ++ni) {
                const int row = m0 + wm * 64 + mi * 16 + g;
                const int col = n0 + wn * 32 + ni * 8 + tig * 2;
#pragma unroll
                for (int h = 0; h < 2; ++h) {
                    __half2 hh;
                    hh.x = __float2half(acc[mi][ni][2 * h + 0] * scale);
                    hh.y = __float2half(acc[mi][ni][2 * h + 1] * scale);
                    *(__half2*)(Ch + (size_t)(row + h * 8) * ldc + col) = hh;
                }
            }
    } else if (EPI == 3) {
#pragma unroll
        for (int mi = 0; mi < 4; ++mi)
#pragma unroll
            for (int h = 0; h < 2; ++h) {
                const int r = m0 + wm * 64 + mi * 16 + g + h * 8;
                float local = 0.0f;
#pragma unroll
                for (int ni = 0; ni < 4; ++ni) {
                    const int col = n0 + wn * 32 + ni * 8 + tig * 2;
                    __half2 hh;
                    hh.x = (col     <= r) ? __float2half(__expf(acc[mi][ni][2 * h + 0]))
                                          : __half(0.0f);
                    hh.y = (col + 1 <= r) ? __float2half(__expf(acc[mi][ni][2 * h + 1]))
                                          : __half(0.0f);
                    *(__half2*)(Ch + (size_t)r * ldc + col) = hh;
                    local += __half2float(hh.x) + __half2float(hh.y);
                }
                local += __shfl_xor_sync(0xffffffffu, local, 1);
                local += __shfl_xor_sync(0xffffffffu, local, 2);
                if (tig == 0) atomicAdd(&Rsum[r], local);
            }
    } else {
#pragma unroll
        for (int mi = 0; mi < 4; ++mi)
#pragma unroll
            for (int h = 0; h < 2; ++h) {
                const int r = m0 + wm * 64 + mi * 16 + g + h * 8;
                const float rv = 1.0f / Rsum[r];
#pragma unroll
                for (int ni = 0; ni < 4; ++ni) {
                    const int col = n0 + wn * 32 + ni * 8 + tig * 2;
                    *(float2*)(Cf + (size_t)r * ldc + col) =
                        make_float2(acc[mi][ni][2 * h + 0] * rv,
                                    acc[mi][ni][2 * h + 1] * rv);
                }
            }
    }
}

// ---------------- kernels ----------------
__global__ void __launch_bounds__(TB, 2)
proj_kernel()
{
    const int z = blockIdx.z;
    const int m0 = blockIdx.y * BM;
    const int n0 = blockIdx.x * BN;
    __half* dst = (z == 0) ? g_Q : (z == 1) ? g_K : g_V;
    const float scale = (z < 2) ? QK_SCALE : 1.0f;
    gemm_body<2>(g_x[z], g_w[z], E_, E_, m0, n0, E_ / BK, scale, nullptr, dst, E_, nullptr);
}

__global__ void __launch_bounds__(TB, 2)
scores_kernel()
{
    if ((int)blockIdx.x > (int)blockIdx.y) return;   // fully above causal diagonal
    const int b = blockIdx.z;
    const size_t qo = (size_t)b * T_ * E_;
    gemm_body<3>(g_Q + qo, g_K + qo, E_, E_,
                 blockIdx.y * BM, blockIdx.x * BN, E_ / BK, 1.0f,
                 nullptr, g_P + (size_t)b * T_ * T_, T_, g_rsum + (size_t)b * T_);
}

__global__ void __launch_bounds__(TB, 2)
out_kernel(float* __restrict__ out)
{
    const int b = blockIdx.z;
    // reversed y: heaviest (largest-kT) blocks get the lowest block ids -> start first
    const int m0 = ((int)gridDim.y - 1 - (int)blockIdx.y) * BM;
    const int kT = (m0 + BM) / BK;   // causal clamp: P cols beyond m0+127 are zero
    gemm_body<4>(g_P + (size_t)b * T_ * T_, g_Vt + (size_t)b * E_ * T_,
                 T_, T_, m0, blockIdx.x * BN, kT, 1.0f,
                 out + (size_t)b * T_ * E_, nullptr, E_, g_rsum + (size_t)b * T_);
}

// zero the rowsum accumulator (re-run every launch -> graph-safe, deterministic)
__global__ void __launch_bounds__(256)
zero_rsum_kernel()
{
    int i = blockIdx.x * 256 + threadIdx.x;
    if (i < M_) g_rsum[i] = 0.0f;
}

// 8 floats per iteration: 2x LDG.128 -> 1x STG.128
__global__ void __launch_bounds__(256)
convert3_kernel(const float* __restrict__ a, const float* __restrict__ b,
                const float* __restrict__ c, __half* __restrict__ o0,
                __half* __restrict__ o1, __half* __restrict__ o2, int n8)
{
    const float* in = (blockIdx.z == 0) ? a : (blockIdx.z == 1) ? b : c;
    __half* out = (blockIdx.z == 0) ? o0 : (blockIdx.z == 1) ? o1 : o2;
    int i = blockIdx.x * blockDim.x + threadIdx.x;
    const int stride = gridDim.x * blockDim.x;
    for (; i < n8; i += stride) {
        float4 x0 = ((const float4*)in)[2 * i];
        float4 x1 = ((const float4*)in)[2 * i + 1];
        __half2 h0 = __floats2half2_rn(x0.x, x0.y);
        __half2 h1 = __floats2half2_rn(x0.z, x0.w);
        __half2 h2 = __floats2half2_rn(x1.x, x1.y);
        __half2 h3 = __floats2half2_rn(x1.z, x1.w);
        uint4 u;
        u.x = *(unsigned*)&h0; u.y = *(unsigned*)&h1;
        u.z = *(unsigned*)&h2; u.w = *(unsigned*)&h3;
        ((uint4*)out)[i] = u;
    }
}

// 64x64 tile, half2 vectorized both sides
__global__ void __launch_bounds__(256)
transpose_v_kernel()
{
    __shared__ __half tile[64][65];
    const int b = blockIdx.z;
    const int e0 = blockIdx.x * 64;
    const int t0 = blockIdx.y * 64;
    const int tx = threadIdx.x & 31;   // half2 column index
    const int ty = threadIdx.x >> 5;   // 0..7
    const __half2* src2 = (const __half2*)(g_V + (size_t)b * T_ * E_);
#pragma unroll
    for (int k = 0; k < 8; ++k) {
        int row = ty + k * 8;                       // t offset
        __half2 v = src2[((size_t)(t0 + row) * E_ + e0) / 2 + tx];
        tile[row][2 * tx]     = v.x;
        tile[row][2 * tx + 1] = v.y;
    }
    __syncthreads();
    __half2* dst2 = (__half2*)(g_Vt + (size_t)b * E_ * T_);
#pragma unroll
    for (int k = 0; k < 8; ++k) {
        int erow = ty + k * 8;                      // e offset
        __half2 w;
        w.x = tile[2 * tx][erow];
        w.y = tile[2 * tx + 1][erow];
        dst2[((size_t)(e0 + erow) * T_ + t0) / 2 + tx] = w;
    }
}

// ---------------- launch ----------------
extern "C" void kernel_launch(void* const* d_in, const int* in_sizes, int n_in,
                              void* d_out, int out_size)
{
    const float* q  = (const float*)d_in[0];
    const float* k  = (const float*)d_in[1];
    const float* v  = (const float*)d_in[2];
    const float* Wq = (const float*)d_in[3];
    const float* Wk = (const float*)d_in[4];
    const float* Wv = (const float*)d_in[5];
    float* out = (float*)d_out;

    cudaFuncSetAttribute(proj_kernel,   cudaFuncAttributeMaxDynamicSharedMemorySize, DSMEM);
    cudaFuncSetAttribute(scores_kernel, cudaFuncAttributeMaxDynamicSharedMemorySize, DSMEM);
    cudaFuncSetAttribute(out_kernel,    cudaFuncAttributeMaxDynamicSharedMemorySize, DSMEM);

    __half *x0, *w0;
    cudaGetSymbolAddress((void**)&x0, g_x);
    cudaGetSymbolAddress((void**)&w0, g_w);
    __half *x1 = x0 + (size_t)M_ * E_, *x2 = x1 + (size_t)M_ * E_;
    __half *w1 = w0 + (size_t)E_ * E_, *w2 = w1 + (size_t)E_ * E_;

    const int n8x = M_ * E_ / 8;
    const int n8w = E_ * E_ / 8;
    convert3_kernel<<<dim3(1024, 1, 3), 256>>>(q, k, v, x0, x1, x2, n8x);
    convert3_kernel<<<dim3(128, 1, 3), 256>>>(Wq, Wk, Wv, w0, w1, w2, n8w);
    zero_rsum_kernel<<<M_ / 256, 256>>>();

    proj_kernel<<<dim3(E_ / BN, M_ / BM, 3), TB, DSMEM>>>();
    transpose_v_kernel<<<dim3(E_ / 64, T_ / 64, B_), 256>>>();
    scores_kernel<<<dim3(T_ / BN, T_ / BM, B_), TB, DSMEM>>>();
    out_kernel<<<dim3(E_ / BN, T_ / BM, B_), TB, DSMEM>>>(out);
}

// round 16
// speedup vs baseline: 1.0668x; 1.0224x over previous
#include <cuda_runtime.h>
#include <cuda_fp16.h>

#define B_ 8
#define T_ 2048
#define E_ 1024
#define M_ (B_ * T_)

#define BM 128
#define BN 128
#define BK 64
#define TB 256
#define NSTAGE 3
#define ASUB 16384u                      // 128x64 fp16
#define STAGE_BYTES (2 * ASUB)           // 32768
#define DSMEM (NSTAGE * STAGE_BYTES)     // 98304
#define QK_SCALE 0.17677669529663687f    // 1024^-0.25

// ---------------- scratch ----------------
__device__ __half g_x[3][(size_t)M_ * E_];
__device__ __half g_w[3][(size_t)E_ * E_];
__device__ __half g_Q[(size_t)M_ * E_];
__device__ __half g_K[(size_t)M_ * E_];
__device__ __half g_Vt[(size_t)B_ * E_ * T_];  // V projection, stored transposed
__device__ __half g_P[(size_t)B_ * T_ * T_];   // exp(scores), unnormalized
__device__ float  g_rsum[(size_t)M_];          // rowsum of g_P (atomic accum)

// ---------------- helpers ----------------
__device__ __forceinline__ unsigned smem_u32(const void* p) {
    return (unsigned)__cvta_generic_to_shared(p);
}
// 128B rows, 8x16B chunks, SW128 xor swizzle: conflict-free for ldmatrix
__device__ __forceinline__ unsigned swz128(int r, int c) {
    return (unsigned)(r * 128 + ((c ^ (r & 7)) * 16));
}
__device__ __forceinline__ void cp_async16(unsigned s, const void* g) {
    asm volatile("cp.async.cg.shared.global [%0], [%1], 16;" :: "r"(s), "l"(g) : "memory");
}
__device__ __forceinline__ void ldsm4(unsigned* r, unsigned addr) {
    asm volatile("ldmatrix.sync.aligned.m8n8.x4.shared.b16 {%0,%1,%2,%3}, [%4];"
                 : "=r"(r[0]), "=r"(r[1]), "=r"(r[2]), "=r"(r[3]) : "r"(addr));
}
__device__ __forceinline__ void mma16816(float* c, const unsigned* a, unsigned b0, unsigned b1) {
    asm volatile(
        "mma.sync.aligned.m16n8k16.row.col.f32.f16.f16.f32 "
        "{%0,%1,%2,%3}, {%4,%5,%6,%7}, {%8,%9}, {%0,%1,%2,%3};"
        : "+f"(c[0]), "+f"(c[1]), "+f"(c[2]), "+f"(c[3])
        : "r"(a[0]), "r"(a[1]), "r"(a[2]), "r"(a[3]), "r"(b0), "r"(b1));
}

// ---------------- single-pass fp16 mma.sync GEMM body (128x128 tile) --------
// D[m0..+128, n0..+128] = A * B^T (both fp16, K-major). Warp tile 64x32.
// EPI 2: scale + fp16 to Ch
// EPI 3: exp(v) with causal mask (col > row -> 0), fp16 to Ch, rowsum atomics to Rsum
// EPI 4: fp32 to Cf, scaled by 1/Rsum[row]
// EPI 5: fp16 to Ch TRANSPOSED per batch: Ch[b*E*T + col*T + (row%T)] (V -> Vt)
template <int EPI>
__device__ __forceinline__ void gemm_body(
    const __half* __restrict__ A, const __half* __restrict__ Bs,
    int lda, int ldb, int m0, int n0, int kTiles, float scale,
    float* __restrict__ Cf, __half* __restrict__ Ch, int ldc,
    float* __restrict__ Rsum)
{
    extern __shared__ __align__(128) char smem[];
    const unsigned sbase = smem_u32(smem);
    const int tid = threadIdx.x;
    const int wid = tid >> 5;
    const int lane = tid & 31;
    const int wm = wid & 1;        // 2 m-tiles of 64
    const int wn = wid >> 1;       // 4 n-tiles of 32

    // per-ks base ldmatrix offsets; row +16 adds exactly 2048 bytes (swizzle-safe)
    unsigned abase[4], bbase[4];
#pragma unroll
    for (int ks = 0; ks < 4; ++ks) {
        abase[ks] = swz128(wm * 64 + (lane & 15), ks * 2 + (lane >> 4));
        bbase[ks] = ASUB + swz128(wn * 32 + ((lane >> 4) & 1) * 8 + (lane & 7),
                                  ks * 2 + ((lane >> 3) & 1));
    }

    float acc[4][4][4];
#pragma unroll
    for (int i = 0; i < 4; ++i)
#pragma unroll
        for (int j = 0; j < 4; ++j)
#pragma unroll
            for (int e = 0; e < 4; ++e) acc[i][j][e] = 0.0f;

    const int cc = tid & 7;        // chunk within row
    const int rr = tid >> 3;       // base row (0..31)

    auto load_stage = [&](int k0, int buf) {
        const unsigned sb = sbase + buf * STAGE_BYTES;
#pragma unroll
        for (int j = 0; j < 4; ++j) {          // A: 128 rows
            const int r = rr + j * 32;
            cp_async16(sb + swz128(r, cc),
                       A + (size_t)(m0 + r) * lda + k0 + cc * 8);
        }
#pragma unroll
        for (int j = 0; j < 4; ++j) {          // B: 128 rows
            const int r = rr + j * 32;
            cp_async16(sb + ASUB + swz128(r, cc),
                       Bs + (size_t)(n0 + r) * ldb + k0 + cc * 8);
        }
    };

    auto compute_ks = [&](unsigned sb, int ks) {
        unsigned a[4][4], b[2][4];
#pragma unroll
        for (int mi = 0; mi < 4; ++mi) ldsm4(a[mi], sb + abase[ks] + mi * 2048);
#pragma unroll
        for (int jp = 0; jp < 2; ++jp) ldsm4(b[jp], sb + bbase[ks] + jp * 2048);
#pragma unroll
        for (int mi = 0; mi < 4; ++mi)
#pragma unroll
            for (int ni = 0; ni < 4; ++ni)
                mma16816(acc[mi][ni], a[mi],
                         b[ni >> 1][(ni & 1) * 2], b[ni >> 1][(ni & 1) * 2 + 1]);
    };

    load_stage(0, 0);
    asm volatile("cp.async.commit_group;" ::: "memory");
    if (kTiles > 1) load_stage(BK, 1);
    asm volatile("cp.async.commit_group;" ::: "memory");

    for (int it = 0; it < kTiles; ++it) {
        asm volatile("cp.async.wait_group 1;" ::: "memory");
        __syncthreads();
        const unsigned sb = sbase + (it % NSTAGE) * STAGE_BYTES;
        compute_ks(sb, 0);
        if (it + 2 < kTiles) load_stage((it + 2) * BK, (it + 2) % NSTAGE);
        asm volatile("cp.async.commit_group;" ::: "memory");
        compute_ks(sb, 1);
        compute_ks(sb, 2);
        compute_ks(sb, 3);
    }

    // epilogue
    const int g = lane >> 2, tig = lane & 3;
    if (EPI == 2) {
#pragma unroll
        for (int mi = 0; mi < 4; ++mi)
#pragma unroll
            for (int ni = 0; ni < 4; ++ni) {
                const int row = m0 + wm * 64 + mi * 16 + g;
                const int col = n0 + wn * 32 + ni * 8 + tig * 2;
#pragma unroll
                for (int h = 0; h < 2; ++h) {
                    __half2 hh;
                    hh.x = __float2half(acc[mi][ni][2 * h + 0] * scale);
                    hh.y = __float2half(acc[mi][ni][2 * h + 1] * scale);
                    *(__half2*)(Ch + (size_t)(row + h * 8) * ldc + col) = hh;
                }
            }
    } else if (EPI == 3) {
#pragma unroll
        for (int mi = 0; mi < 4; ++mi)
#pragma unroll
            for (int h = 0; h < 2; ++h) {
                const int r = m0 + wm * 64 + mi * 16 + g + h * 8;
                float local = 0.0f;
#pragma unroll
                for (int ni = 0; ni < 4; ++ni) {
                    const int col = n0 + wn * 32 + ni * 8 + tig * 2;
                    __half2 hh;
                    hh.x = (col     <= r) ? __float2half(__expf(acc[mi][ni][2 * h + 0]))
                                          : __half(0.0f);
                    hh.y = (col + 1 <= r) ? __float2half(__expf(acc[mi][ni][2 * h + 1]))
                                          : __half(0.0f);
                    *(__half2*)(Ch + (size_t)r * ldc + col) = hh;
                    local += __half2float(hh.x) + __half2float(hh.y);
                }
                local += __shfl_xor_sync(0xffffffffu, local, 1);
                local += __shfl_xor_sync(0xffffffffu, local, 2);
                if (tig == 0) atomicAdd(&Rsum[r], local);
            }
    } else if (EPI == 4) {
#pragma unroll
        for (int mi = 0; mi < 4; ++mi)
#pragma unroll
            for (int h = 0; h < 2; ++h) {
                const int r = m0 + wm * 64 + mi * 16 + g + h * 8;
                const float rv = 1.0f / Rsum[r];
#pragma unroll
                for (int ni = 0; ni < 4; ++ni) {
                    const int col = n0 + wn * 32 + ni * 8 + tig * 2;
                    *(float2*)(Cf + (size_t)r * ldc + col) =
                        make_float2(acc[mi][ni][2 * h + 0] * rv,
                                    acc[mi][ni][2 * h + 1] * rv);
                }
            }
    } else {   // EPI == 5: transposed store V -> Vt[b][col][t]
        const int bb = m0 >> 11;                  // m0 / T_, constant per CTA
        __half* vt = Ch + (size_t)bb * E_ * T_;
#pragma unroll
        for (int mi = 0; mi < 4; ++mi)
#pragma unroll
            for (int h = 0; h < 2; ++h) {
                const int tt = (m0 & (T_ - 1)) + wm * 64 + mi * 16 + g + h * 8;
#pragma unroll
                for (int ni = 0; ni < 4; ++ni) {
                    const int col = n0 + wn * 32 + ni * 8 + tig * 2;
                    vt[(size_t)col * T_ + tt]       = __float2half(acc[mi][ni][2 * h + 0]);
                    vt[(size_t)(col + 1) * T_ + tt] = __float2half(acc[mi][ni][2 * h + 1]);
                }
            }
    }
}

// ---------------- kernels ----------------
__global__ void __launch_bounds__(TB, 2)
proj_kernel()
{
    const int z = blockIdx.z;
    const int m0 = blockIdx.y * BM;
    const int n0 = blockIdx.x * BN;
    if (z == 0)
        gemm_body<2>(g_x[0], g_w[0], E_, E_, m0, n0, E_ / BK, QK_SCALE,
                     nullptr, g_Q, E_, nullptr);
    else if (z == 1)
        gemm_body<2>(g_x[1], g_w[1], E_, E_, m0, n0, E_ / BK, QK_SCALE,
                     nullptr, g_K, E_, nullptr);
    else
        gemm_body<5>(g_x[2], g_w[2], E_, E_, m0, n0, E_ / BK, 1.0f,
                     nullptr, g_Vt, T_, nullptr);
}

__global__ void __launch_bounds__(TB, 2)
scores_kernel()
{
    if ((int)blockIdx.x > (int)blockIdx.y) return;   // fully above causal diagonal
    const int b = blockIdx.z;
    const size_t qo = (size_t)b * T_ * E_;
    gemm_body<3>(g_Q + qo, g_K + qo, E_, E_,
                 blockIdx.y * BM, blockIdx.x * BN, E_ / BK, 1.0f,
                 nullptr, g_P + (size_t)b * T_ * T_, T_, g_rsum + (size_t)b * T_);
}

__global__ void __launch_bounds__(TB, 2)
out_kernel(float* __restrict__ out)
{
    const int b = blockIdx.z;
    // reversed y: heaviest (largest-kT) blocks get the lowest block ids -> start first
    const int m0 = ((int)gridDim.y - 1 - (int)blockIdx.y) * BM;
    const int kT = (m0 + BM) / BK;   // causal clamp: P cols beyond m0+127 are zero
    gemm_body<4>(g_P + (size_t)b * T_ * T_, g_Vt + (size_t)b * E_ * T_,
                 T_, T_, m0, blockIdx.x * BN, kT, 1.0f,
                 out + (size_t)b * T_ * E_, nullptr, E_, g_rsum + (size_t)b * T_);
}

// 8 floats per iteration: 2x LDG.128 -> 1x STG.128
// zero_rsum == 1: also zero g_rsum (weights-convert grid covers M_ threads)
template <int ZERO_RSUM>
__global__ void __launch_bounds__(256)
convert3_kernel(const float* __restrict__ a, const float* __restrict__ b,
                const float* __restrict__ c, __half* __restrict__ o0,
                __half* __restrict__ o1, __half* __restrict__ o2, int n8)
{
    if (ZERO_RSUM && blockIdx.z == 0) {
        int zi = blockIdx.x * 256 + threadIdx.x;
        if (zi < M_) g_rsum[zi] = 0.0f;
    }
    const float* in = (blockIdx.z == 0) ? a : (blockIdx.z == 1) ? b : c;
    __half* out = (blockIdx.z == 0) ? o0 : (blockIdx.z == 1) ? o1 : o2;
    int i = blockIdx.x * blockDim.x + threadIdx.x;
    const int stride = gridDim.x * blockDim.x;
    for (; i < n8; i += stride) {
        float4 x0 = ((const float4*)in)[2 * i];
        float4 x1 = ((const float4*)in)[2 * i + 1];
        __half2 h0 = __floats2half2_rn(x0.x, x0.y);
        __half2 h1 = __floats2half2_rn(x0.z, x0.w);
        __half2 h2 = __floats2half2_rn(x1.x, x1.y);
        __half2 h3 = __floats2half2_rn(x1.z, x1.w);
        uint4 u;
        u.x = *(unsigned*)&h0; u.y = *(unsigned*)&h1;
        u.z = *(unsigned*)&h2; u.w = *(unsigned*)&h3;
        ((uint4*)out)[i] = u;
    }
}

// ---------------- launch ----------------
extern "C" void kernel_launch(void* const* d_in, const int* in_sizes, int n_in,
                              void* d_out, int out_size)
{
    const float* q  = (const float*)d_in[0];
    const float* k  = (const float*)d_in[1];
    const float* v  = (const float*)d_in[2];
    const float* Wq = (const float*)d_in[3];
    const float* Wk = (const float*)d_in[4];
    const float* Wv = (const float*)d_in[5];
    float* out = (float*)d_out;

    cudaFuncSetAttribute(proj_kernel,   cudaFuncAttributeMaxDynamicSharedMemorySize, DSMEM);
    cudaFuncSetAttribute(scores_kernel, cudaFuncAttributeMaxDynamicSharedMemorySize, DSMEM);
    cudaFuncSetAttribute(out_kernel,    cudaFuncAttributeMaxDynamicSharedMemorySize, DSMEM);

    __half *x0, *w0;
    cudaGetSymbolAddress((void**)&x0, g_x);
    cudaGetSymbolAddress((void**)&w0, g_w);
    __half *x1 = x0 + (size_t)M_ * E_, *x2 = x1 + (size_t)M_ * E_;
    __half *w1 = w0 + (size_t)E_ * E_, *w2 = w1 + (size_t)E_ * E_;

    const int n8x = M_ * E_ / 8;
    const int n8w = E_ * E_ / 8;
    convert3_kernel<0><<<dim3(2048, 1, 3), 256>>>(q, k, v, x0, x1, x2, n8x);
    convert3_kernel<1><<<dim3(128, 1, 3), 256>>>(Wq, Wk, Wv, w0, w1, w2, n8w);

    proj_kernel<<<dim3(E_ / BN, M_ / BM, 3), TB, DSMEM>>>();
    scores_kernel<<<dim3(T_ / BN, T_ / BM, B_), TB, DSMEM>>>();
    out_kernel<<<dim3(E_ / BN, T_ / BM, B_), TB, DSMEM>>>(out);
}